// round 6
// baseline (speedup 1.0000x reference)
#include <cuda_runtime.h>
#include <cuda_fp16.h>

#define N_NODES  100000
#define N_EDGES  1600000
#define N_GRAPHS 64
#define ELL_W    64          // max in-degree pad (P(deg>64) ~ 1e-20)

// ---------------- scratch (device globals) ----------------------------------
__device__ __align__(256) __half2 g_x1h  [N_NODES * 4];   // n_feat*invout, fp16 (8 vals)
__device__ __align__(256) __half2 g_h1s  [N_NODES * 8];   // relu(h1)*invout, fp16 (16 vals)
__device__ __align__(256) __half2 g_z3h  [N_NODES * 8];   // (h2*invout)@W3, fp16 (10 vals)
__device__ __align__(256) float   g_invin [N_NODES];
__device__ __align__(256) float   g_invout[N_NODES];
__device__ __align__(256) int     g_degout[N_NODES];
__device__ __align__(256) int     g_degin [N_NODES];
__device__ __align__(256) int     g_ell   [(size_t)N_NODES * ELL_W];  // 25.6 MB
__device__ __align__(256) float   g_gsum [N_GRAPHS * 10];

__device__ __forceinline__ void acc_h2(float& a0, float& a1, unsigned bits) {
    __half2 h = *reinterpret_cast<__half2*>(&bits);
    float2 f = __half22float2(h);
    a0 += f.x; a1 += f.y;
}

// ---------------- build ------------------------------------------------------

__global__ void k_zero() {
    int i = blockIdx.x * blockDim.x + threadIdx.x;
    if (i < N_NODES) { g_degout[i] = 0; g_degin[i] = 0; }
    if (i < N_GRAPHS * 10) g_gsum[i] = 0.f;
}

// ONE edge pass: degree count + ELL fill (atomic return = slot index)
__global__ void k_fill(const int* __restrict__ src, const int* __restrict__ dst) {
    int t = blockIdx.x * blockDim.x + threadIdx.x;
    int base = t * 4;
    if (base >= N_EDGES) return;
    int4 s = *(const int4*)(src + base);
    int4 d = *(const int4*)(dst + base);
    atomicAdd(&g_degout[s.x], 1);
    atomicAdd(&g_degout[s.y], 1);
    atomicAdd(&g_degout[s.z], 1);
    atomicAdd(&g_degout[s.w], 1);
    int p0 = atomicAdd(&g_degin[d.x], 1);
    int p1 = atomicAdd(&g_degin[d.y], 1);
    int p2 = atomicAdd(&g_degin[d.z], 1);
    int p3 = atomicAdd(&g_degin[d.w], 1);
    g_ell[(size_t)d.x * ELL_W + p0] = s.x;
    g_ell[(size_t)d.y * ELL_W + p1] = s.y;
    g_ell[(size_t)d.z * ELL_W + p2] = s.z;
    g_ell[(size_t)d.w * ELL_W + p3] = s.w;
}

// inv-sqrt degrees + pre-scale node features by inv_sqrt_out -> fp16
__global__ void k_prep(const float* __restrict__ n_feat) {
    int i = blockIdx.x * blockDim.x + threadIdx.x;
    if (i >= N_NODES) return;
    float io = rsqrtf(fmaxf((float)g_degout[i], 1.f));
    float ii = rsqrtf(fmaxf((float)g_degin [i], 1.f));
    g_invin[i]  = ii;
    g_invout[i] = io;
    const float4* xr = (const float4*)(n_feat + (size_t)i * 8);
    float4 a = xr[0], b = xr[1];
    __half2 hv[4];
    hv[0] = __floats2half2_rn(a.x * io, a.y * io);
    hv[1] = __floats2half2_rn(a.z * io, a.w * io);
    hv[2] = __floats2half2_rn(b.x * io, b.y * io);
    hv[3] = __floats2half2_rn(b.z * io, b.w * io);
    *(uint4*)(g_x1h + (size_t)i * 4) = *(uint4*)hv;
}

// ---------------- fused gather + dense layers (4 lanes per node) --------------

// Layer 1: acc8 = sum x1h[src]; h1s = relu(acc*ii @ W1 + b1)*io -> fp16
__global__ void k_layer1(const float* __restrict__ W1, const float* __restrict__ b1) {
    __shared__ float sW[8 * 16];
    __shared__ float sb[16];
    int t = threadIdx.x;
    if (t < 128) sW[t] = W1[t];
    if (t < 16)  sb[t] = b1[t];
    __syncthreads();
    int node = blockIdx.x * (blockDim.x >> 2) + (t >> 2);
    int l4 = t & 3;
    bool ok = (node < N_NODES);
    float a[8];
    #pragma unroll
    for (int j = 0; j < 8; j++) a[j] = 0.f;
    if (ok) {
        int deg = g_degin[node];
        const int* row = g_ell + (size_t)node * ELL_W;
        for (int e = l4; e < deg; e += 4) {
            int s = row[e];
            uint4 u = *(const uint4*)(g_x1h + (size_t)s * 4);
            acc_h2(a[0], a[1], u.x); acc_h2(a[2], a[3], u.y);
            acc_h2(a[4], a[5], u.z); acc_h2(a[6], a[7], u.w);
        }
    }
    // butterfly reduce over the 4-lane subgroup -> all lanes hold full sums
    #pragma unroll
    for (int off = 1; off <= 2; off <<= 1)
        #pragma unroll
        for (int j = 0; j < 8; j++)
            a[j] += __shfl_xor_sync(0xffffffffu, a[j], off);
    if (!ok) return;
    float ii = g_invin[node], io = g_invout[node];
    // lane l4 computes outputs [l4*4, l4*4+4)
    float acc4[4];
    #pragma unroll
    for (int j = 0; j < 4; j++) acc4[j] = sb[l4 * 4 + j];
    #pragma unroll
    for (int k = 0; k < 8; k++) {
        float ak = a[k] * ii;
        #pragma unroll
        for (int j = 0; j < 4; j++)
            acc4[j] = fmaf(ak, sW[k * 16 + l4 * 4 + j], acc4[j]);
    }
    __half2 hv[2];
    hv[0] = __floats2half2_rn(fmaxf(acc4[0], 0.f) * io, fmaxf(acc4[1], 0.f) * io);
    hv[1] = __floats2half2_rn(fmaxf(acc4[2], 0.f) * io, fmaxf(acc4[3], 0.f) * io);
    *(uint2*)(g_h1s + (size_t)node * 8 + l4 * 2) = *(uint2*)hv;  // 4 lanes -> 32B row
}

// Layer 2+3a: acc16 = sum h1s[src]; h2 = relu(acc*ii @ W2 + b2);
//             z3 = (h2*io) @ W3 -> fp16
__global__ void k_layer2(const float* __restrict__ W2, const float* __restrict__ b2,
                         const float* __restrict__ W3) {
    __shared__ float sW2[16 * 32];
    __shared__ float sb2[32];
    __shared__ float sW3[32 * 10];
    int t = threadIdx.x;
    for (int j = t; j < 16 * 32; j += blockDim.x) sW2[j] = W2[j];
    for (int j = t; j < 32 * 10; j += blockDim.x) sW3[j] = W3[j];
    if (t < 32) sb2[t] = b2[t];
    __syncthreads();
    int node = blockIdx.x * (blockDim.x >> 2) + (t >> 2);
    int l4 = t & 3;
    bool ok = (node < N_NODES);
    float a[16];
    #pragma unroll
    for (int j = 0; j < 16; j++) a[j] = 0.f;
    if (ok) {
        int deg = g_degin[node];
        const int* row = g_ell + (size_t)node * ELL_W;
        for (int e = l4; e < deg; e += 4) {
            int s = row[e];
            const uint4* p = (const uint4*)(g_h1s + (size_t)s * 8);
            uint4 u = p[0], v = p[1];
            acc_h2(a[0],  a[1],  u.x); acc_h2(a[2],  a[3],  u.y);
            acc_h2(a[4],  a[5],  u.z); acc_h2(a[6],  a[7],  u.w);
            acc_h2(a[8],  a[9],  v.x); acc_h2(a[10], a[11], v.y);
            acc_h2(a[12], a[13], v.z); acc_h2(a[14], a[15], v.w);
        }
    }
    #pragma unroll
    for (int off = 1; off <= 2; off <<= 1)
        #pragma unroll
        for (int j = 0; j < 16; j++)
            a[j] += __shfl_xor_sync(0xffffffffu, a[j], off);
    float ii = ok ? g_invin[node] : 0.f;
    float io = ok ? g_invout[node] : 0.f;
    // lane l4 computes h2 outputs [l4*8, l4*8+8) and partial z3
    float acc8[8];
    #pragma unroll
    for (int j = 0; j < 8; j++) acc8[j] = sb2[l4 * 8 + j];
    #pragma unroll
    for (int k = 0; k < 16; k++) {
        float ak = a[k] * ii;
        #pragma unroll
        for (int j = 0; j < 8; j++)
            acc8[j] = fmaf(ak, sW2[k * 32 + l4 * 8 + j], acc8[j]);
    }
    float z[10];
    #pragma unroll
    for (int j = 0; j < 10; j++) z[j] = 0.f;
    #pragma unroll
    for (int k = 0; k < 8; k++) {
        float h = fmaxf(acc8[k], 0.f) * io;
        #pragma unroll
        for (int j = 0; j < 10; j++)
            z[j] = fmaf(h, sW3[(l4 * 8 + k) * 10 + j], z[j]);
    }
    // reduce z partials over subgroup
    #pragma unroll
    for (int off = 1; off <= 2; off <<= 1)
        #pragma unroll
        for (int j = 0; j < 10; j++)
            z[j] += __shfl_xor_sync(0xffffffffu, z[j], off);
    if (!ok || l4 != 0) return;
    __half2 hv[5];
    #pragma unroll
    for (int v = 0; v < 5; v++)
        hv[v] = __floats2half2_rn(z[2*v], z[2*v+1]);
    __half2* o = g_z3h + (size_t)node * 8;
    *(uint4*)(o) = *(uint4*)(hv);
    *(unsigned*)(o + 4) = *(unsigned*)(hv + 4);
}

// Layer 3b + pool (4 lanes per node; 1024-thread blocks = 256 nodes/block)
__global__ void k_layer3(const int* __restrict__ gids) {
    __shared__ float ssum[N_GRAPHS * 10];
    int t = threadIdx.x;
    for (int j = t; j < N_GRAPHS * 10; j += blockDim.x) ssum[j] = 0.f;
    __syncthreads();
    int node = blockIdx.x * (blockDim.x >> 2) + (t >> 2);
    int l4 = t & 3;
    bool ok = (node < N_NODES);
    float v[10];
    #pragma unroll
    for (int j = 0; j < 10; j++) v[j] = 0.f;
    if (ok) {
        int deg = g_degin[node];
        const int* row = g_ell + (size_t)node * ELL_W;
        for (int e = l4; e < deg; e += 4) {
            int s = row[e];
            const __half2* r = g_z3h + (size_t)s * 8;
            uint4 u = *(const uint4*)r;
            unsigned w = *(const unsigned*)(r + 4);
            acc_h2(v[0], v[1], u.x); acc_h2(v[2], v[3], u.y);
            acc_h2(v[4], v[5], u.z); acc_h2(v[6], v[7], u.w);
            acc_h2(v[8], v[9], w);
        }
    }
    #pragma unroll
    for (int off = 1; off <= 2; off <<= 1)
        #pragma unroll
        for (int j = 0; j < 10; j++)
            v[j] += __shfl_xor_sync(0xffffffffu, v[j], off);
    if (ok) {
        float ii = g_invin[node];
        int g = gids[node];
        // feature-split atomics across the 4-lane subgroup
        #pragma unroll
        for (int j = 0; j < 3; j++) {
            int f = l4 + j * 4;
            if (f < 10) atomicAdd(&ssum[g * 10 + f], v[f] * ii);
        }
    }
    __syncthreads();
    for (int j = t; j < N_GRAPHS * 10; j += blockDim.x) {
        float s = ssum[j];
        if (s != 0.f) atomicAdd(&g_gsum[j], s);
    }
}

__device__ __forceinline__ int lowerb(const int* __restrict__ a, int n, int v) {
    int lo = 0, hi = n;
    while (lo < hi) {
        int m = (lo + hi) >> 1;
        if (a[m] < v) lo = m + 1; else hi = m;
    }
    return lo;
}

__global__ void k_final(const int* __restrict__ gids, const float* __restrict__ b3,
                        float* __restrict__ out) {
    int i = blockIdx.x * blockDim.x + threadIdx.x;
    if (i >= N_GRAPHS * 10) return;
    int g = i / 10, j = i % 10;
    int lo = lowerb(gids, N_NODES, g);
    int hi = lowerb(gids, N_NODES, g + 1);
    float cnt = (float)(hi - lo);
    out[i] = g_gsum[i] / fmaxf(cnt, 1.f) + b3[j];
}

// ---------------- launch ------------------------------------------------------
extern "C" void kernel_launch(void* const* d_in, const int* in_sizes, int n_in,
                              void* d_out, int out_size) {
    const float* n_feat = (const float*)d_in[0];
    const int*   src    = (const int*)  d_in[1];
    const int*   dst    = (const int*)  d_in[2];
    const int*   gids   = (const int*)  d_in[3];
    const float* W1     = (const float*)d_in[4];
    const float* b1     = (const float*)d_in[5];
    const float* W2     = (const float*)d_in[6];
    const float* b2     = (const float*)d_in[7];
    const float* W3     = (const float*)d_in[8];
    const float* b3     = (const float*)d_in[9];
    float* out = (float*)d_out;

    const int TB = 256;
    const int nb  = (N_NODES + TB - 1) / TB;
    const int eb4 = (N_EDGES / 4 + TB - 1) / TB;
    const int cb  = (N_NODES * 4 + TB - 1) / TB;     // 4 lanes/node, 256-thread blocks
    const int pb  = (N_NODES * 4 + 1023) / 1024;     // 4 lanes/node, 1024-thread blocks

    k_zero   <<<nb, TB>>>();
    k_fill   <<<eb4, TB>>>(src, dst);
    k_prep   <<<nb, TB>>>(n_feat);
    k_layer1 <<<cb, TB>>>(W1, b1);
    k_layer2 <<<cb, TB>>>(W2, b2, W3);
    k_layer3 <<<pb, 1024>>>(gids);
    k_final  <<<1, N_GRAPHS * 10>>>(gids, b3, out);
}

// round 7
// speedup vs baseline: 1.1625x; 1.1625x over previous
#include <cuda_runtime.h>
#include <cuda_fp16.h>

#define N_NODES  100000
#define N_EDGES  1600000
#define N_GRAPHS 64
#define ELL_W    64          // max in-degree pad (P(deg>64) ~ 1e-20)
#define NBLK     296         // 2 blocks per SM (148 SMs) -> balanced
#define TB       256

// ---------------- scratch (device globals) ----------------------------------
__device__ __align__(256) __half2 g_x1h  [N_NODES * 4];   // n_feat*invout, fp16 (8 vals)
__device__ __align__(256) __half2 g_h1s  [N_NODES * 8];   // relu(h1)*invout, fp16 (16 vals)
__device__ __align__(256) __half2 g_z3h  [N_NODES * 8];   // (h2*invout)@W3, fp16 (10 vals)
__device__ __align__(256) float   g_invin [N_NODES];
__device__ __align__(256) float   g_invout[N_NODES];
__device__ __align__(256) int     g_degout[N_NODES];
__device__ __align__(256) int     g_degin [N_NODES];
__device__ __align__(256) int     g_ell   [(size_t)N_NODES * ELL_W];  // 25.6 MB
__device__ __align__(256) float   g_gsum [N_GRAPHS * 10];

__device__ __forceinline__ void acc_h2(float& a0, float& a1, unsigned bits) {
    __half2 h = *reinterpret_cast<__half2*>(&bits);
    float2 f = __half22float2(h);
    a0 += f.x; a1 += f.y;
}

// ---------------- build ------------------------------------------------------

__global__ void k_zero() {
    int stride = gridDim.x * blockDim.x;
    for (int i = blockIdx.x * blockDim.x + threadIdx.x; i < N_NODES; i += stride) {
        g_degout[i] = 0; g_degin[i] = 0;
        if (i < N_GRAPHS * 10) g_gsum[i] = 0.f;
    }
}

// ONE edge pass: degree count + ELL fill (atomic return = slot index)
__global__ void k_fill(const int* __restrict__ src, const int* __restrict__ dst) {
    int stride = gridDim.x * blockDim.x;
    const int nq = N_EDGES / 4;
    for (int t = blockIdx.x * blockDim.x + threadIdx.x; t < nq; t += stride) {
        int base = t * 4;
        int4 s = *(const int4*)(src + base);
        int4 d = *(const int4*)(dst + base);
        atomicAdd(&g_degout[s.x], 1);
        atomicAdd(&g_degout[s.y], 1);
        atomicAdd(&g_degout[s.z], 1);
        atomicAdd(&g_degout[s.w], 1);
        int p0 = atomicAdd(&g_degin[d.x], 1);
        int p1 = atomicAdd(&g_degin[d.y], 1);
        int p2 = atomicAdd(&g_degin[d.z], 1);
        int p3 = atomicAdd(&g_degin[d.w], 1);
        g_ell[(size_t)d.x * ELL_W + p0] = s.x;
        g_ell[(size_t)d.y * ELL_W + p1] = s.y;
        g_ell[(size_t)d.z * ELL_W + p2] = s.z;
        g_ell[(size_t)d.w * ELL_W + p3] = s.w;
    }
}

// inv-sqrt degrees + pre-scale node features by inv_sqrt_out -> fp16
__global__ void k_prep(const float* __restrict__ n_feat) {
    int stride = gridDim.x * blockDim.x;
    for (int i = blockIdx.x * blockDim.x + threadIdx.x; i < N_NODES; i += stride) {
        float io = rsqrtf(fmaxf((float)g_degout[i], 1.f));
        float ii = rsqrtf(fmaxf((float)g_degin [i], 1.f));
        g_invin[i]  = ii;
        g_invout[i] = io;
        const float4* xr = (const float4*)(n_feat + (size_t)i * 8);
        float4 a = xr[0], b = xr[1];
        __half2 hv[4];
        hv[0] = __floats2half2_rn(a.x * io, a.y * io);
        hv[1] = __floats2half2_rn(a.z * io, a.w * io);
        hv[2] = __floats2half2_rn(b.x * io, b.y * io);
        hv[3] = __floats2half2_rn(b.z * io, b.w * io);
        *(uint4*)(g_x1h + (size_t)i * 4) = *(uint4*)hv;
    }
}

// ---------------- fused gather + dense layers (thread per node, grid-stride) --

// Layer 1: acc8 = sum x1h[src]; h1s = relu(acc*ii @ W1 + b1)*io -> fp16
__global__ void k_layer1(const float* __restrict__ W1, const float* __restrict__ b1) {
    __shared__ float sW[8 * 16];
    __shared__ float sb[16];
    int t = threadIdx.x;
    if (t < 128) sW[t] = W1[t];
    if (t < 16)  sb[t] = b1[t];
    __syncthreads();
    int stride = gridDim.x * blockDim.x;
    for (int i = blockIdx.x * blockDim.x + t; i < N_NODES; i += stride) {
        int deg = g_degin[i];
        const int* row = g_ell + (size_t)i * ELL_W;
        float a[8];
        #pragma unroll
        for (int j = 0; j < 8; j++) a[j] = 0.f;
        int e = 0;
        for (; e + 4 <= deg; e += 4) {
            int4 s = *(const int4*)(row + e);             // 256B-aligned row
            uint4 u0 = *(const uint4*)(g_x1h + (size_t)s.x * 4);
            uint4 u1 = *(const uint4*)(g_x1h + (size_t)s.y * 4);
            uint4 u2 = *(const uint4*)(g_x1h + (size_t)s.z * 4);
            uint4 u3 = *(const uint4*)(g_x1h + (size_t)s.w * 4);
            acc_h2(a[0], a[1], u0.x); acc_h2(a[2], a[3], u0.y);
            acc_h2(a[4], a[5], u0.z); acc_h2(a[6], a[7], u0.w);
            acc_h2(a[0], a[1], u1.x); acc_h2(a[2], a[3], u1.y);
            acc_h2(a[4], a[5], u1.z); acc_h2(a[6], a[7], u1.w);
            acc_h2(a[0], a[1], u2.x); acc_h2(a[2], a[3], u2.y);
            acc_h2(a[4], a[5], u2.z); acc_h2(a[6], a[7], u2.w);
            acc_h2(a[0], a[1], u3.x); acc_h2(a[2], a[3], u3.y);
            acc_h2(a[4], a[5], u3.z); acc_h2(a[6], a[7], u3.w);
        }
        for (; e < deg; e++) {
            int s = row[e];
            uint4 u = *(const uint4*)(g_x1h + (size_t)s * 4);
            acc_h2(a[0], a[1], u.x); acc_h2(a[2], a[3], u.y);
            acc_h2(a[4], a[5], u.z); acc_h2(a[6], a[7], u.w);
        }
        float ii = g_invin[i], io = g_invout[i];
        float acc[16];
        #pragma unroll
        for (int j = 0; j < 16; j++) acc[j] = sb[j];
        #pragma unroll
        for (int k = 0; k < 8; k++) {
            float ak = a[k] * ii;
            #pragma unroll
            for (int j = 0; j < 16; j++)
                acc[j] = fmaf(ak, sW[k * 16 + j], acc[j]);
        }
        __half2 hv[8];
        #pragma unroll
        for (int v = 0; v < 8; v++)
            hv[v] = __floats2half2_rn(fmaxf(acc[2*v], 0.f) * io,
                                      fmaxf(acc[2*v+1], 0.f) * io);
        uint4* o = (uint4*)(g_h1s + (size_t)i * 8);
        o[0] = *(uint4*)(hv);
        o[1] = *(uint4*)(hv + 4);
    }
}

// Layer 2+3a: acc16 = sum h1s[src]; h2 = relu(acc*ii @ W2 + b2);
//             z3 = (h2*io) @ W3 -> fp16
__global__ void k_layer2(const float* __restrict__ W2, const float* __restrict__ b2,
                         const float* __restrict__ W3) {
    __shared__ float sW2[16 * 32];
    __shared__ float sb2[32];
    __shared__ float sW3[32 * 10];
    int t = threadIdx.x;
    for (int j = t; j < 16 * 32; j += blockDim.x) sW2[j] = W2[j];
    for (int j = t; j < 32 * 10; j += blockDim.x) sW3[j] = W3[j];
    if (t < 32) sb2[t] = b2[t];
    __syncthreads();
    int stride = gridDim.x * blockDim.x;
    for (int i = blockIdx.x * blockDim.x + t; i < N_NODES; i += stride) {
        int deg = g_degin[i];
        const int* row = g_ell + (size_t)i * ELL_W;
        float a[16];
        #pragma unroll
        for (int j = 0; j < 16; j++) a[j] = 0.f;
        int e = 0;
        for (; e + 4 <= deg; e += 4) {
            int4 s = *(const int4*)(row + e);
            const uint4* p0 = (const uint4*)(g_h1s + (size_t)s.x * 8);
            const uint4* p1 = (const uint4*)(g_h1s + (size_t)s.y * 8);
            const uint4* p2 = (const uint4*)(g_h1s + (size_t)s.z * 8);
            const uint4* p3 = (const uint4*)(g_h1s + (size_t)s.w * 8);
            uint4 u0 = p0[0], v0 = p0[1];
            uint4 u1 = p1[0], v1 = p1[1];
            uint4 u2 = p2[0], v2 = p2[1];
            uint4 u3 = p3[0], v3 = p3[1];
            acc_h2(a[0],  a[1],  u0.x); acc_h2(a[2],  a[3],  u0.y);
            acc_h2(a[4],  a[5],  u0.z); acc_h2(a[6],  a[7],  u0.w);
            acc_h2(a[8],  a[9],  v0.x); acc_h2(a[10], a[11], v0.y);
            acc_h2(a[12], a[13], v0.z); acc_h2(a[14], a[15], v0.w);
            acc_h2(a[0],  a[1],  u1.x); acc_h2(a[2],  a[3],  u1.y);
            acc_h2(a[4],  a[5],  u1.z); acc_h2(a[6],  a[7],  u1.w);
            acc_h2(a[8],  a[9],  v1.x); acc_h2(a[10], a[11], v1.y);
            acc_h2(a[12], a[13], v1.z); acc_h2(a[14], a[15], v1.w);
            acc_h2(a[0],  a[1],  u2.x); acc_h2(a[2],  a[3],  u2.y);
            acc_h2(a[4],  a[5],  u2.z); acc_h2(a[6],  a[7],  u2.w);
            acc_h2(a[8],  a[9],  v2.x); acc_h2(a[10], a[11], v2.y);
            acc_h2(a[12], a[13], v2.z); acc_h2(a[14], a[15], v2.w);
            acc_h2(a[0],  a[1],  u3.x); acc_h2(a[2],  a[3],  u3.y);
            acc_h2(a[4],  a[5],  u3.z); acc_h2(a[6],  a[7],  u3.w);
            acc_h2(a[8],  a[9],  v3.x); acc_h2(a[10], a[11], v3.y);
            acc_h2(a[12], a[13], v3.z); acc_h2(a[14], a[15], v3.w);
        }
        for (; e < deg; e++) {
            int s = row[e];
            const uint4* p = (const uint4*)(g_h1s + (size_t)s * 8);
            uint4 u = p[0], v = p[1];
            acc_h2(a[0],  a[1],  u.x); acc_h2(a[2],  a[3],  u.y);
            acc_h2(a[4],  a[5],  u.z); acc_h2(a[6],  a[7],  u.w);
            acc_h2(a[8],  a[9],  v.x); acc_h2(a[10], a[11], v.y);
            acc_h2(a[12], a[13], v.z); acc_h2(a[14], a[15], v.w);
        }
        float ii = g_invin[i], io = g_invout[i];
        float acc[32];
        #pragma unroll
        for (int j = 0; j < 32; j++) acc[j] = sb2[j];
        #pragma unroll
        for (int k = 0; k < 16; k++) {
            float ak = a[k] * ii;
            #pragma unroll
            for (int j = 0; j < 32; j++)
                acc[j] = fmaf(ak, sW2[k * 32 + j], acc[j]);
        }
        float z[10];
        #pragma unroll
        for (int j = 0; j < 10; j++) z[j] = 0.f;
        #pragma unroll
        for (int k = 0; k < 32; k++) {
            float h = fmaxf(acc[k], 0.f) * io;
            #pragma unroll
            for (int j = 0; j < 10; j++)
                z[j] = fmaf(h, sW3[k * 10 + j], z[j]);
        }
        __half2 hv[5];
        #pragma unroll
        for (int v = 0; v < 5; v++)
            hv[v] = __floats2half2_rn(z[2*v], z[2*v+1]);
        __half2* o = g_z3h + (size_t)i * 8;
        *(uint4*)(o) = *(uint4*)(hv);
        *(unsigned*)(o + 4) = *(unsigned*)(hv + 4);
    }
}

// Layer 3b + pool (thread per node, grid-stride; per-block smem pool)
__global__ void k_layer3(const int* __restrict__ gids) {
    __shared__ float ssum[N_GRAPHS * 10];
    int t = threadIdx.x;
    for (int j = t; j < N_GRAPHS * 10; j += blockDim.x) ssum[j] = 0.f;
    __syncthreads();
    int stride = gridDim.x * blockDim.x;
    for (int i = blockIdx.x * blockDim.x + t; i < N_NODES; i += stride) {
        float v[10];
        #pragma unroll
        for (int j = 0; j < 10; j++) v[j] = 0.f;
        int deg = g_degin[i];
        const int* row = g_ell + (size_t)i * ELL_W;
        int e = 0;
        for (; e + 4 <= deg; e += 4) {
            int4 s = *(const int4*)(row + e);
            const __half2* r0 = g_z3h + (size_t)s.x * 8;
            const __half2* r1 = g_z3h + (size_t)s.y * 8;
            const __half2* r2 = g_z3h + (size_t)s.z * 8;
            const __half2* r3 = g_z3h + (size_t)s.w * 8;
            uint4 u0 = *(const uint4*)r0;  unsigned w0 = *(const unsigned*)(r0 + 4);
            uint4 u1 = *(const uint4*)r1;  unsigned w1 = *(const unsigned*)(r1 + 4);
            uint4 u2 = *(const uint4*)r2;  unsigned w2 = *(const unsigned*)(r2 + 4);
            uint4 u3 = *(const uint4*)r3;  unsigned w3 = *(const unsigned*)(r3 + 4);
            acc_h2(v[0], v[1], u0.x); acc_h2(v[2], v[3], u0.y);
            acc_h2(v[4], v[5], u0.z); acc_h2(v[6], v[7], u0.w); acc_h2(v[8], v[9], w0);
            acc_h2(v[0], v[1], u1.x); acc_h2(v[2], v[3], u1.y);
            acc_h2(v[4], v[5], u1.z); acc_h2(v[6], v[7], u1.w); acc_h2(v[8], v[9], w1);
            acc_h2(v[0], v[1], u2.x); acc_h2(v[2], v[3], u2.y);
            acc_h2(v[4], v[5], u2.z); acc_h2(v[6], v[7], u2.w); acc_h2(v[8], v[9], w2);
            acc_h2(v[0], v[1], u3.x); acc_h2(v[2], v[3], u3.y);
            acc_h2(v[4], v[5], u3.z); acc_h2(v[6], v[7], u3.w); acc_h2(v[8], v[9], w3);
        }
        for (; e < deg; e++) {
            int s = row[e];
            const __half2* r = g_z3h + (size_t)s * 8;
            uint4 u = *(const uint4*)r;
            unsigned w = *(const unsigned*)(r + 4);
            acc_h2(v[0], v[1], u.x); acc_h2(v[2], v[3], u.y);
            acc_h2(v[4], v[5], u.z); acc_h2(v[6], v[7], u.w); acc_h2(v[8], v[9], w);
        }
        float ii = g_invin[i];
        #pragma unroll
        for (int j = 0; j < 10; j++) v[j] *= ii;
        int g = gids[i];
        // warp-uniform graph id fast path (graph_ids sorted)
        int leader = __shfl_sync(0xffffffffu, g, 0);
        bool uni = __all_sync(0xffffffffu, g == leader);
        if (uni) {
            #pragma unroll
            for (int j = 0; j < 10; j++) {
                float s = v[j];
                #pragma unroll
                for (int off = 16; off > 0; off >>= 1)
                    s += __shfl_xor_sync(0xffffffffu, s, off);
                if ((t & 31) == 0) atomicAdd(&ssum[leader * 10 + j], s);
            }
        } else {
            #pragma unroll
            for (int j = 0; j < 10; j++)
                atomicAdd(&ssum[g * 10 + j], v[j]);
        }
    }
    __syncthreads();
    for (int j = t; j < N_GRAPHS * 10; j += blockDim.x) {
        float s = ssum[j];
        if (s != 0.f) atomicAdd(&g_gsum[j], s);
    }
}

__device__ __forceinline__ int lowerb(const int* __restrict__ a, int n, int v) {
    int lo = 0, hi = n;
    while (lo < hi) {
        int m = (lo + hi) >> 1;
        if (a[m] < v) lo = m + 1; else hi = m;
    }
    return lo;
}

__global__ void k_final(const int* __restrict__ gids, const float* __restrict__ b3,
                        float* __restrict__ out) {
    int i = blockIdx.x * blockDim.x + threadIdx.x;
    if (i >= N_GRAPHS * 10) return;
    int g = i / 10, j = i % 10;
    int lo = lowerb(gids, N_NODES, g);
    int hi = lowerb(gids, N_NODES, g + 1);
    float cnt = (float)(hi - lo);
    out[i] = g_gsum[i] / fmaxf(cnt, 1.f) + b3[j];
}

// ---------------- launch ------------------------------------------------------
extern "C" void kernel_launch(void* const* d_in, const int* in_sizes, int n_in,
                              void* d_out, int out_size) {
    const float* n_feat = (const float*)d_in[0];
    const int*   src    = (const int*)  d_in[1];
    const int*   dst    = (const int*)  d_in[2];
    const int*   gids   = (const int*)  d_in[3];
    const float* W1     = (const float*)d_in[4];
    const float* b1     = (const float*)d_in[5];
    const float* W2     = (const float*)d_in[6];
    const float* b2     = (const float*)d_in[7];
    const float* W3     = (const float*)d_in[8];
    const float* b3     = (const float*)d_in[9];
    float* out = (float*)d_out;

    k_zero   <<<NBLK, TB>>>();
    k_fill   <<<NBLK, TB>>>(src, dst);
    k_prep   <<<NBLK, TB>>>(n_feat);
    k_layer1 <<<NBLK, TB>>>(W1, b1);
    k_layer2 <<<NBLK, TB>>>(W2, b2, W3);
    k_layer3 <<<NBLK, TB>>>(gids);
    k_final  <<<1, N_GRAPHS * 10>>>(gids, b3, out);
}

// round 8
// speedup vs baseline: 1.2519x; 1.0769x over previous
#include <cuda_runtime.h>
#include <cuda_fp16.h>

#define N_NODES  100000
#define N_EDGES  1600000
#define N_GRAPHS 64
#define ELL_W    64          // max in-degree pad (P(deg>64) ~ 1e-20)

// ---------------- scratch (device globals) ----------------------------------
__device__ __align__(256) __half2  g_x1h  [N_NODES * 4];   // n_feat*invout, fp16 (8 vals)
__device__ __align__(256) unsigned g_h1f  [N_NODES * 4];   // relu(h1)*invout, fp8 e4m3 (16 vals = 16B)
__device__ __align__(256) __half2  g_z3h  [N_NODES * 8];   // (h2*invout)@W3, fp16 (10 vals)
__device__ __align__(256) float    g_invin [N_NODES];
__device__ __align__(256) float    g_invout[N_NODES];
__device__ __align__(256) int      g_degout[N_NODES];
__device__ __align__(256) int      g_degin [N_NODES];
__device__ __align__(256) int      g_ell   [(size_t)N_NODES * ELL_W];  // 25.6 MB
__device__ __align__(256) float    g_gsum [N_GRAPHS * 10];

__device__ __forceinline__ void acc_h2(float& a0, float& a1, unsigned bits) {
    __half2 h = *reinterpret_cast<__half2*>(&bits);
    float2 f = __half22float2(h);
    a0 += f.x; a1 += f.y;
}

// encode two floats -> e4m3x2 (hi=v1, lo=v0)
__device__ __forceinline__ unsigned short enc_e4m3x2(float v1, float v0) {
    unsigned short r;
    asm("cvt.rn.satfinite.e4m3x2.f32 %0, %1, %2;" : "=h"(r) : "f"(v1), "f"(v0));
    return r;
}
// decode 4 fp8 (one word) and accumulate into a[0..3]
__device__ __forceinline__ void acc_fp8x4(float& a0, float& a1, float& a2, float& a3,
                                          unsigned w) {
    unsigned short lo = (unsigned short)(w & 0xffffu);
    unsigned short hi = (unsigned short)(w >> 16);
    unsigned r0, r1;
    asm("cvt.rn.f16x2.e4m3x2 %0, %1;" : "=r"(r0) : "h"(lo));
    asm("cvt.rn.f16x2.e4m3x2 %0, %1;" : "=r"(r1) : "h"(hi));
    acc_h2(a0, a1, r0);
    acc_h2(a2, a3, r1);
}

// ---------------- build ------------------------------------------------------

__global__ void k_zero() {
    int i = blockIdx.x * blockDim.x + threadIdx.x;
    if (i < N_NODES) { g_degout[i] = 0; g_degin[i] = 0; }
    if (i < N_GRAPHS * 10) g_gsum[i] = 0.f;
}

// ONE edge pass: degree count + ELL fill (atomic return = slot index), 8 edges/thread
__global__ void k_fill(const int* __restrict__ src, const int* __restrict__ dst) {
    int t = blockIdx.x * blockDim.x + threadIdx.x;
    int base = t * 8;
    if (base >= N_EDGES) return;
    int4 sa = *(const int4*)(src + base);
    int4 sb = *(const int4*)(src + base + 4);
    int4 da = *(const int4*)(dst + base);
    int4 db = *(const int4*)(dst + base + 4);
    atomicAdd(&g_degout[sa.x], 1); atomicAdd(&g_degout[sa.y], 1);
    atomicAdd(&g_degout[sa.z], 1); atomicAdd(&g_degout[sa.w], 1);
    atomicAdd(&g_degout[sb.x], 1); atomicAdd(&g_degout[sb.y], 1);
    atomicAdd(&g_degout[sb.z], 1); atomicAdd(&g_degout[sb.w], 1);
    int p0 = atomicAdd(&g_degin[da.x], 1);
    int p1 = atomicAdd(&g_degin[da.y], 1);
    int p2 = atomicAdd(&g_degin[da.z], 1);
    int p3 = atomicAdd(&g_degin[da.w], 1);
    int p4 = atomicAdd(&g_degin[db.x], 1);
    int p5 = atomicAdd(&g_degin[db.y], 1);
    int p6 = atomicAdd(&g_degin[db.z], 1);
    int p7 = atomicAdd(&g_degin[db.w], 1);
    g_ell[(size_t)da.x * ELL_W + p0] = sa.x;
    g_ell[(size_t)da.y * ELL_W + p1] = sa.y;
    g_ell[(size_t)da.z * ELL_W + p2] = sa.z;
    g_ell[(size_t)da.w * ELL_W + p3] = sa.w;
    g_ell[(size_t)db.x * ELL_W + p4] = sb.x;
    g_ell[(size_t)db.y * ELL_W + p5] = sb.y;
    g_ell[(size_t)db.z * ELL_W + p6] = sb.z;
    g_ell[(size_t)db.w * ELL_W + p7] = sb.w;
}

// inv-sqrt degrees + pre-scale node features by inv_sqrt_out -> fp16
__global__ void k_prep(const float* __restrict__ n_feat) {
    int i = blockIdx.x * blockDim.x + threadIdx.x;
    if (i >= N_NODES) return;
    float io = rsqrtf(fmaxf((float)g_degout[i], 1.f));
    float ii = rsqrtf(fmaxf((float)g_degin [i], 1.f));
    g_invin[i]  = ii;
    g_invout[i] = io;
    const float4* xr = (const float4*)(n_feat + (size_t)i * 8);
    float4 a = xr[0], b = xr[1];
    __half2 hv[4];
    hv[0] = __floats2half2_rn(a.x * io, a.y * io);
    hv[1] = __floats2half2_rn(a.z * io, a.w * io);
    hv[2] = __floats2half2_rn(b.x * io, b.y * io);
    hv[3] = __floats2half2_rn(b.z * io, b.w * io);
    *(uint4*)(g_x1h + (size_t)i * 4) = *(uint4*)hv;
}

// ---------------- fused gather + dense layers (thread per node) ---------------

// Layer 1: acc8 = sum x1h[src]; h1 = relu(acc*ii @ W1 + b1)*io -> fp8
__global__ void k_layer1(const float* __restrict__ W1, const float* __restrict__ b1) {
    __shared__ float sW[8 * 16];
    __shared__ float sb[16];
    int t = threadIdx.x;
    if (t < 128) sW[t] = W1[t];
    if (t < 16)  sb[t] = b1[t];
    __syncthreads();
    int i = blockIdx.x * blockDim.x + t;
    if (i >= N_NODES) return;
    int deg = g_degin[i];
    const int* row = g_ell + (size_t)i * ELL_W;
    float a[8];
    #pragma unroll
    for (int j = 0; j < 8; j++) a[j] = 0.f;
    int e = 0;
    for (; e + 4 <= deg; e += 4) {
        int4 s = *(const int4*)(row + e);                 // 256B-aligned row
        uint4 u0 = *(const uint4*)(g_x1h + (size_t)s.x * 4);
        uint4 u1 = *(const uint4*)(g_x1h + (size_t)s.y * 4);
        uint4 u2 = *(const uint4*)(g_x1h + (size_t)s.z * 4);
        uint4 u3 = *(const uint4*)(g_x1h + (size_t)s.w * 4);
        acc_h2(a[0], a[1], u0.x); acc_h2(a[2], a[3], u0.y);
        acc_h2(a[4], a[5], u0.z); acc_h2(a[6], a[7], u0.w);
        acc_h2(a[0], a[1], u1.x); acc_h2(a[2], a[3], u1.y);
        acc_h2(a[4], a[5], u1.z); acc_h2(a[6], a[7], u1.w);
        acc_h2(a[0], a[1], u2.x); acc_h2(a[2], a[3], u2.y);
        acc_h2(a[4], a[5], u2.z); acc_h2(a[6], a[7], u2.w);
        acc_h2(a[0], a[1], u3.x); acc_h2(a[2], a[3], u3.y);
        acc_h2(a[4], a[5], u3.z); acc_h2(a[6], a[7], u3.w);
    }
    for (; e < deg; e++) {
        int s = row[e];
        uint4 u = *(const uint4*)(g_x1h + (size_t)s * 4);
        acc_h2(a[0], a[1], u.x); acc_h2(a[2], a[3], u.y);
        acc_h2(a[4], a[5], u.z); acc_h2(a[6], a[7], u.w);
    }
    float ii = g_invin[i], io = g_invout[i];
    float acc[16];
    #pragma unroll
    for (int j = 0; j < 16; j++) acc[j] = sb[j];
    #pragma unroll
    for (int k = 0; k < 8; k++) {
        float ak = a[k] * ii;
        #pragma unroll
        for (int j = 0; j < 16; j++)
            acc[j] = fmaf(ak, sW[k * 16 + j], acc[j]);
    }
    // encode 16 outputs as fp8 e4m3 -> one uint4
    unsigned w[4];
    #pragma unroll
    for (int v = 0; v < 4; v++) {
        float v0 = fmaxf(acc[4*v+0], 0.f) * io;
        float v1 = fmaxf(acc[4*v+1], 0.f) * io;
        float v2 = fmaxf(acc[4*v+2], 0.f) * io;
        float v3 = fmaxf(acc[4*v+3], 0.f) * io;
        unsigned short lo = enc_e4m3x2(v1, v0);
        unsigned short hi = enc_e4m3x2(v3, v2);
        w[v] = (unsigned)lo | ((unsigned)hi << 16);
    }
    *(uint4*)(g_h1f + (size_t)i * 4) = make_uint4(w[0], w[1], w[2], w[3]);
}

// Layer 2+3a: acc16 = sum h1f[src] (fp8->fp32); h2 = relu(acc*ii @ W2 + b2);
//             z3 = (h2*io) @ W3 -> fp16
__global__ void k_layer2(const float* __restrict__ W2, const float* __restrict__ b2,
                         const float* __restrict__ W3) {
    __shared__ float sW2[16 * 32];
    __shared__ float sb2[32];
    __shared__ float sW3[32 * 10];
    int t = threadIdx.x;
    for (int j = t; j < 16 * 32; j += blockDim.x) sW2[j] = W2[j];
    for (int j = t; j < 32 * 10; j += blockDim.x) sW3[j] = W3[j];
    if (t < 32) sb2[t] = b2[t];
    __syncthreads();
    int i = blockIdx.x * blockDim.x + t;
    if (i >= N_NODES) return;
    int deg = g_degin[i];
    const int* row = g_ell + (size_t)i * ELL_W;
    float a[16];
    #pragma unroll
    for (int j = 0; j < 16; j++) a[j] = 0.f;
    int e = 0;
    for (; e + 4 <= deg; e += 4) {
        int4 s = *(const int4*)(row + e);
        uint4 u0 = *(const uint4*)(g_h1f + (size_t)s.x * 4);
        uint4 u1 = *(const uint4*)(g_h1f + (size_t)s.y * 4);
        uint4 u2 = *(const uint4*)(g_h1f + (size_t)s.z * 4);
        uint4 u3 = *(const uint4*)(g_h1f + (size_t)s.w * 4);
        acc_fp8x4(a[0], a[1], a[2], a[3], u0.x);
        acc_fp8x4(a[4], a[5], a[6], a[7], u0.y);
        acc_fp8x4(a[8], a[9], a[10], a[11], u0.z);
        acc_fp8x4(a[12], a[13], a[14], a[15], u0.w);
        acc_fp8x4(a[0], a[1], a[2], a[3], u1.x);
        acc_fp8x4(a[4], a[5], a[6], a[7], u1.y);
        acc_fp8x4(a[8], a[9], a[10], a[11], u1.z);
        acc_fp8x4(a[12], a[13], a[14], a[15], u1.w);
        acc_fp8x4(a[0], a[1], a[2], a[3], u2.x);
        acc_fp8x4(a[4], a[5], a[6], a[7], u2.y);
        acc_fp8x4(a[8], a[9], a[10], a[11], u2.z);
        acc_fp8x4(a[12], a[13], a[14], a[15], u2.w);
        acc_fp8x4(a[0], a[1], a[2], a[3], u3.x);
        acc_fp8x4(a[4], a[5], a[6], a[7], u3.y);
        acc_fp8x4(a[8], a[9], a[10], a[11], u3.z);
        acc_fp8x4(a[12], a[13], a[14], a[15], u3.w);
    }
    for (; e < deg; e++) {
        int s = row[e];
        uint4 u = *(const uint4*)(g_h1f + (size_t)s * 4);
        acc_fp8x4(a[0], a[1], a[2], a[3], u.x);
        acc_fp8x4(a[4], a[5], a[6], a[7], u.y);
        acc_fp8x4(a[8], a[9], a[10], a[11], u.z);
        acc_fp8x4(a[12], a[13], a[14], a[15], u.w);
    }
    float ii = g_invin[i], io = g_invout[i];
    float acc[32];
    #pragma unroll
    for (int j = 0; j < 32; j++) acc[j] = sb2[j];
    #pragma unroll
    for (int k = 0; k < 16; k++) {
        float ak = a[k] * ii;
        #pragma unroll
        for (int j = 0; j < 32; j++)
            acc[j] = fmaf(ak, sW2[k * 32 + j], acc[j]);
    }
    float z[10];
    #pragma unroll
    for (int j = 0; j < 10; j++) z[j] = 0.f;
    #pragma unroll
    for (int k = 0; k < 32; k++) {
        float h = fmaxf(acc[k], 0.f) * io;
        #pragma unroll
        for (int j = 0; j < 10; j++)
            z[j] = fmaf(h, sW3[k * 10 + j], z[j]);
    }
    __half2 hv[5];
    #pragma unroll
    for (int v = 0; v < 5; v++)
        hv[v] = __floats2half2_rn(z[2*v], z[2*v+1]);
    __half2* o = g_z3h + (size_t)i * 8;
    *(uint4*)(o) = *(uint4*)(hv);
    *(unsigned*)(o + 4) = *(unsigned*)(hv + 4);
}

// Layer 3b + pool (thread per node; smem per-graph sums)
__global__ void k_layer3(const int* __restrict__ gids) {
    __shared__ float ssum[N_GRAPHS * 10];
    int t = threadIdx.x;
    for (int j = t; j < N_GRAPHS * 10; j += blockDim.x) ssum[j] = 0.f;
    __syncthreads();
    int i = blockIdx.x * blockDim.x + t;
    float v[10];
    int g = -1;
    if (i < N_NODES) {
        #pragma unroll
        for (int j = 0; j < 10; j++) v[j] = 0.f;
        int deg = g_degin[i];
        const int* row = g_ell + (size_t)i * ELL_W;
        int e = 0;
        for (; e + 4 <= deg; e += 4) {
            int4 s = *(const int4*)(row + e);
            const __half2* r0 = g_z3h + (size_t)s.x * 8;
            const __half2* r1 = g_z3h + (size_t)s.y * 8;
            const __half2* r2 = g_z3h + (size_t)s.z * 8;
            const __half2* r3 = g_z3h + (size_t)s.w * 8;
            uint4 u0 = *(const uint4*)r0;  unsigned w0 = *(const unsigned*)(r0 + 4);
            uint4 u1 = *(const uint4*)r1;  unsigned w1 = *(const unsigned*)(r1 + 4);
            uint4 u2 = *(const uint4*)r2;  unsigned w2 = *(const unsigned*)(r2 + 4);
            uint4 u3 = *(const uint4*)r3;  unsigned w3 = *(const unsigned*)(r3 + 4);
            acc_h2(v[0], v[1], u0.x); acc_h2(v[2], v[3], u0.y);
            acc_h2(v[4], v[5], u0.z); acc_h2(v[6], v[7], u0.w); acc_h2(v[8], v[9], w0);
            acc_h2(v[0], v[1], u1.x); acc_h2(v[2], v[3], u1.y);
            acc_h2(v[4], v[5], u1.z); acc_h2(v[6], v[7], u1.w); acc_h2(v[8], v[9], w1);
            acc_h2(v[0], v[1], u2.x); acc_h2(v[2], v[3], u2.y);
            acc_h2(v[4], v[5], u2.z); acc_h2(v[6], v[7], u2.w); acc_h2(v[8], v[9], w2);
            acc_h2(v[0], v[1], u3.x); acc_h2(v[2], v[3], u3.y);
            acc_h2(v[4], v[5], u3.z); acc_h2(v[6], v[7], u3.w); acc_h2(v[8], v[9], w3);
        }
        for (; e < deg; e++) {
            int s = row[e];
            const __half2* r = g_z3h + (size_t)s * 8;
            uint4 u = *(const uint4*)r;
            unsigned w = *(const unsigned*)(r + 4);
            acc_h2(v[0], v[1], u.x); acc_h2(v[2], v[3], u.y);
            acc_h2(v[4], v[5], u.z); acc_h2(v[6], v[7], u.w); acc_h2(v[8], v[9], w);
        }
        float ii = g_invin[i];
        #pragma unroll
        for (int j = 0; j < 10; j++) v[j] *= ii;
        g = gids[i];
    } else {
        #pragma unroll
        for (int j = 0; j < 10; j++) v[j] = 0.f;
    }
    int leader = __shfl_sync(0xffffffffu, g, 0);
    bool uni = __all_sync(0xffffffffu, g == leader);
    if (uni && leader >= 0) {
        #pragma unroll
        for (int j = 0; j < 10; j++) {
            float s = v[j];
            #pragma unroll
            for (int off = 16; off > 0; off >>= 1)
                s += __shfl_xor_sync(0xffffffffu, s, off);
            if ((t & 31) == 0) atomicAdd(&ssum[leader * 10 + j], s);
        }
    } else if (g >= 0) {
        #pragma unroll
        for (int j = 0; j < 10; j++)
            atomicAdd(&ssum[g * 10 + j], v[j]);
    }
    __syncthreads();
    for (int j = t; j < N_GRAPHS * 10; j += blockDim.x) {
        float s = ssum[j];
        if (s != 0.f) atomicAdd(&g_gsum[j], s);
    }
}

__device__ __forceinline__ int lowerb(const int* __restrict__ a, int n, int v) {
    int lo = 0, hi = n;
    while (lo < hi) {
        int m = (lo + hi) >> 1;
        if (a[m] < v) lo = m + 1; else hi = m;
    }
    return lo;
}

__global__ void k_final(const int* __restrict__ gids, const float* __restrict__ b3,
                        float* __restrict__ out) {
    int i = blockIdx.x * blockDim.x + threadIdx.x;
    if (i >= N_GRAPHS * 10) return;
    int g = i / 10, j = i % 10;
    int lo = lowerb(gids, N_NODES, g);
    int hi = lowerb(gids, N_NODES, g + 1);
    float cnt = (float)(hi - lo);
    out[i] = g_gsum[i] / fmaxf(cnt, 1.f) + b3[j];
}

// ---------------- launch ------------------------------------------------------
extern "C" void kernel_launch(void* const* d_in, const int* in_sizes, int n_in,
                              void* d_out, int out_size) {
    const float* n_feat = (const float*)d_in[0];
    const int*   src    = (const int*)  d_in[1];
    const int*   dst    = (const int*)  d_in[2];
    const int*   gids   = (const int*)  d_in[3];
    const float* W1     = (const float*)d_in[4];
    const float* b1     = (const float*)d_in[5];
    const float* W2     = (const float*)d_in[6];
    const float* b2     = (const float*)d_in[7];
    const float* W3     = (const float*)d_in[8];
    const float* b3     = (const float*)d_in[9];
    float* out = (float*)d_out;

    const int TB = 256;
    const int nb  = (N_NODES + TB - 1) / TB;
    const int eb8 = (N_EDGES / 8 + TB - 1) / TB;
    const int pb  = (N_NODES + 1023) / 1024;

    k_zero   <<<nb, TB>>>();
    k_fill   <<<eb8, TB>>>(src, dst);
    k_prep   <<<nb, TB>>>(n_feat);
    k_layer1 <<<nb, TB>>>(W1, b1);
    k_layer2 <<<nb, TB>>>(W2, b2, W3);
    k_layer3 <<<pb, 1024>>>(gids);
    k_final  <<<1, N_GRAPHS * 10>>>(gids, b3, out);
}

// round 9
// speedup vs baseline: 1.2602x; 1.0066x over previous
#include <cuda_runtime.h>
#include <cuda_fp16.h>

#define N_NODES  100000
#define N_EDGES  1600000
#define N_GRAPHS 64
#define ELL_W    64          // max in-degree pad (P(deg>64) ~ 1e-20)

// ---------------- scratch (device globals; zero-init at load) ----------------
// INVARIANT: g_degout, g_degin, g_gsum, g_done are zero on entry to every
// kernel_launch call and are restored to zero by the end of it.
__device__ __align__(256) __half2  g_x1h  [N_NODES * 4];   // n_feat*invout, fp16 (8 vals)
__device__ __align__(256) __half2  g_h1s  [N_NODES * 8];   // relu(h1)*invout, fp16 (16 vals)
__device__ __align__(256) __half2  g_z3h  [N_NODES * 8];   // (h2*invout)@W3, fp16 (10 vals)
__device__ __align__(256) float    g_invin [N_NODES];
__device__ __align__(256) float    g_invout[N_NODES];
__device__ __align__(256) int      g_degout[N_NODES];
__device__ __align__(256) int      g_degin [N_NODES];
__device__ __align__(256) int      g_ell   [(size_t)N_NODES * ELL_W];  // 25.6 MB
__device__ __align__(256) float    g_gsum [N_GRAPHS * 10];
__device__                int      g_done;

__device__ __forceinline__ void acc_h2(float& a0, float& a1, unsigned bits) {
    __half2 h = *reinterpret_cast<__half2*>(&bits);
    float2 f = __half22float2(h);
    a0 += f.x; a1 += f.y;
}

// ---------------- build ------------------------------------------------------

// ONE edge pass: degree count + ELL fill (atomic return = slot index), 8 edges/thread
__global__ void k_fill(const int* __restrict__ src, const int* __restrict__ dst) {
    int t = blockIdx.x * blockDim.x + threadIdx.x;
    int base = t * 8;
    if (base >= N_EDGES) return;
    int4 sa = *(const int4*)(src + base);
    int4 sb = *(const int4*)(src + base + 4);
    int4 da = *(const int4*)(dst + base);
    int4 db = *(const int4*)(dst + base + 4);
    atomicAdd(&g_degout[sa.x], 1); atomicAdd(&g_degout[sa.y], 1);
    atomicAdd(&g_degout[sa.z], 1); atomicAdd(&g_degout[sa.w], 1);
    atomicAdd(&g_degout[sb.x], 1); atomicAdd(&g_degout[sb.y], 1);
    atomicAdd(&g_degout[sb.z], 1); atomicAdd(&g_degout[sb.w], 1);
    int p0 = atomicAdd(&g_degin[da.x], 1);
    int p1 = atomicAdd(&g_degin[da.y], 1);
    int p2 = atomicAdd(&g_degin[da.z], 1);
    int p3 = atomicAdd(&g_degin[da.w], 1);
    int p4 = atomicAdd(&g_degin[db.x], 1);
    int p5 = atomicAdd(&g_degin[db.y], 1);
    int p6 = atomicAdd(&g_degin[db.z], 1);
    int p7 = atomicAdd(&g_degin[db.w], 1);
    g_ell[(size_t)da.x * ELL_W + p0] = sa.x;
    g_ell[(size_t)da.y * ELL_W + p1] = sa.y;
    g_ell[(size_t)da.z * ELL_W + p2] = sa.z;
    g_ell[(size_t)da.w * ELL_W + p3] = sa.w;
    g_ell[(size_t)db.x * ELL_W + p4] = sb.x;
    g_ell[(size_t)db.y * ELL_W + p5] = sb.y;
    g_ell[(size_t)db.z * ELL_W + p6] = sb.z;
    g_ell[(size_t)db.w * ELL_W + p7] = sb.w;
}

// inv-sqrt degrees + pre-scale node features by inv_sqrt_out -> fp16
__global__ void k_prep(const float* __restrict__ n_feat) {
    int i = blockIdx.x * blockDim.x + threadIdx.x;
    if (i >= N_NODES) return;
    float io = rsqrtf(fmaxf((float)g_degout[i], 1.f));
    float ii = rsqrtf(fmaxf((float)g_degin [i], 1.f));
    g_invin[i]  = ii;
    g_invout[i] = io;
    const float4* xr = (const float4*)(n_feat + (size_t)i * 8);
    float4 a = xr[0], b = xr[1];
    __half2 hv[4];
    hv[0] = __floats2half2_rn(a.x * io, a.y * io);
    hv[1] = __floats2half2_rn(a.z * io, a.w * io);
    hv[2] = __floats2half2_rn(b.x * io, b.y * io);
    hv[3] = __floats2half2_rn(b.z * io, b.w * io);
    *(uint4*)(g_x1h + (size_t)i * 4) = *(uint4*)hv;
}

// ---------------- fused gather + dense layers (thread per node) ---------------

// Layer 1: acc8 = sum x1h[src]; h1s = relu(acc*ii @ W1 + b1)*io -> fp16
__global__ void k_layer1(const float* __restrict__ W1, const float* __restrict__ b1) {
    __shared__ float sW[8 * 16];
    __shared__ float sb[16];
    int t = threadIdx.x;
    if (t < 128) sW[t] = W1[t];
    if (t < 16)  sb[t] = b1[t];
    __syncthreads();
    int i = blockIdx.x * blockDim.x + t;
    if (i >= N_NODES) return;
    int deg = g_degin[i];
    const int* row = g_ell + (size_t)i * ELL_W;
    float a[8];
    #pragma unroll
    for (int j = 0; j < 8; j++) a[j] = 0.f;
    int e = 0;
    for (; e + 4 <= deg; e += 4) {
        int4 s = *(const int4*)(row + e);                 // 256B-aligned row
        uint4 u0 = *(const uint4*)(g_x1h + (size_t)s.x * 4);
        uint4 u1 = *(const uint4*)(g_x1h + (size_t)s.y * 4);
        uint4 u2 = *(const uint4*)(g_x1h + (size_t)s.z * 4);
        uint4 u3 = *(const uint4*)(g_x1h + (size_t)s.w * 4);
        acc_h2(a[0], a[1], u0.x); acc_h2(a[2], a[3], u0.y);
        acc_h2(a[4], a[5], u0.z); acc_h2(a[6], a[7], u0.w);
        acc_h2(a[0], a[1], u1.x); acc_h2(a[2], a[3], u1.y);
        acc_h2(a[4], a[5], u1.z); acc_h2(a[6], a[7], u1.w);
        acc_h2(a[0], a[1], u2.x); acc_h2(a[2], a[3], u2.y);
        acc_h2(a[4], a[5], u2.z); acc_h2(a[6], a[7], u2.w);
        acc_h2(a[0], a[1], u3.x); acc_h2(a[2], a[3], u3.y);
        acc_h2(a[4], a[5], u3.z); acc_h2(a[6], a[7], u3.w);
    }
    for (; e < deg; e++) {
        int s = row[e];
        uint4 u = *(const uint4*)(g_x1h + (size_t)s * 4);
        acc_h2(a[0], a[1], u.x); acc_h2(a[2], a[3], u.y);
        acc_h2(a[4], a[5], u.z); acc_h2(a[6], a[7], u.w);
    }
    float ii = g_invin[i], io = g_invout[i];
    float acc[16];
    #pragma unroll
    for (int j = 0; j < 16; j++) acc[j] = sb[j];
    #pragma unroll
    for (int k = 0; k < 8; k++) {
        float ak = a[k] * ii;
        #pragma unroll
        for (int j = 0; j < 16; j++)
            acc[j] = fmaf(ak, sW[k * 16 + j], acc[j]);
    }
    __half2 hv[8];
    #pragma unroll
    for (int v = 0; v < 8; v++)
        hv[v] = __floats2half2_rn(fmaxf(acc[2*v], 0.f) * io,
                                  fmaxf(acc[2*v+1], 0.f) * io);
    uint4* o = (uint4*)(g_h1s + (size_t)i * 8);
    o[0] = *(uint4*)(hv);
    o[1] = *(uint4*)(hv + 4);
}

// Layer 2+3a: acc16 = sum h1s[src] (fp16->fp32); h2 = relu(acc*ii @ W2 + b2);
//             z3 = (h2*io) @ W3 -> fp16
__global__ void k_layer2(const float* __restrict__ W2, const float* __restrict__ b2,
                         const float* __restrict__ W3) {
    __shared__ float sW2[16 * 32];
    __shared__ float sb2[32];
    __shared__ float sW3[32 * 10];
    int t = threadIdx.x;
    for (int j = t; j < 16 * 32; j += blockDim.x) sW2[j] = W2[j];
    for (int j = t; j < 32 * 10; j += blockDim.x) sW3[j] = W3[j];
    if (t < 32) sb2[t] = b2[t];
    __syncthreads();
    int i = blockIdx.x * blockDim.x + t;
    if (i >= N_NODES) return;
    int deg = g_degin[i];
    const int* row = g_ell + (size_t)i * ELL_W;
    float a[16];
    #pragma unroll
    for (int j = 0; j < 16; j++) a[j] = 0.f;
    int e = 0;
    for (; e + 4 <= deg; e += 4) {
        int4 s = *(const int4*)(row + e);
        const uint4* p0 = (const uint4*)(g_h1s + (size_t)s.x * 8);
        const uint4* p1 = (const uint4*)(g_h1s + (size_t)s.y * 8);
        const uint4* p2 = (const uint4*)(g_h1s + (size_t)s.z * 8);
        const uint4* p3 = (const uint4*)(g_h1s + (size_t)s.w * 8);
        uint4 u0 = p0[0], v0 = p0[1];
        uint4 u1 = p1[0], v1 = p1[1];
        uint4 u2 = p2[0], v2 = p2[1];
        uint4 u3 = p3[0], v3 = p3[1];
        acc_h2(a[0],  a[1],  u0.x); acc_h2(a[2],  a[3],  u0.y);
        acc_h2(a[4],  a[5],  u0.z); acc_h2(a[6],  a[7],  u0.w);
        acc_h2(a[8],  a[9],  v0.x); acc_h2(a[10], a[11], v0.y);
        acc_h2(a[12], a[13], v0.z); acc_h2(a[14], a[15], v0.w);
        acc_h2(a[0],  a[1],  u1.x); acc_h2(a[2],  a[3],  u1.y);
        acc_h2(a[4],  a[5],  u1.z); acc_h2(a[6],  a[7],  u1.w);
        acc_h2(a[8],  a[9],  v1.x); acc_h2(a[10], a[11], v1.y);
        acc_h2(a[12], a[13], v1.z); acc_h2(a[14], a[15], v1.w);
        acc_h2(a[0],  a[1],  u2.x); acc_h2(a[2],  a[3],  u2.y);
        acc_h2(a[4],  a[5],  u2.z); acc_h2(a[6],  a[7],  u2.w);
        acc_h2(a[8],  a[9],  v2.x); acc_h2(a[10], a[11], v2.y);
        acc_h2(a[12], a[13], v2.z); acc_h2(a[14], a[15], v2.w);
        acc_h2(a[0],  a[1],  u3.x); acc_h2(a[2],  a[3],  u3.y);
        acc_h2(a[4],  a[5],  u3.z); acc_h2(a[6],  a[7],  u3.w);
        acc_h2(a[8],  a[9],  v3.x); acc_h2(a[10], a[11], v3.y);
        acc_h2(a[12], a[13], v3.z); acc_h2(a[14], a[15], v3.w);
    }
    for (; e < deg; e++) {
        int s = row[e];
        const uint4* p = (const uint4*)(g_h1s + (size_t)s * 8);
        uint4 u = p[0], v = p[1];
        acc_h2(a[0],  a[1],  u.x); acc_h2(a[2],  a[3],  u.y);
        acc_h2(a[4],  a[5],  u.z); acc_h2(a[6],  a[7],  u.w);
        acc_h2(a[8],  a[9],  v.x); acc_h2(a[10], a[11], v.y);
        acc_h2(a[12], a[13], v.z); acc_h2(a[14], a[15], v.w);
    }
    float ii = g_invin[i], io = g_invout[i];
    float acc[32];
    #pragma unroll
    for (int j = 0; j < 32; j++) acc[j] = sb2[j];
    #pragma unroll
    for (int k = 0; k < 16; k++) {
        float ak = a[k] * ii;
        #pragma unroll
        for (int j = 0; j < 32; j++)
            acc[j] = fmaf(ak, sW2[k * 32 + j], acc[j]);
    }
    float z[10];
    #pragma unroll
    for (int j = 0; j < 10; j++) z[j] = 0.f;
    #pragma unroll
    for (int k = 0; k < 32; k++) {
        float h = fmaxf(acc[k], 0.f) * io;
        #pragma unroll
        for (int j = 0; j < 10; j++)
            z[j] = fmaf(h, sW3[k * 10 + j], z[j]);
    }
    __half2 hv[5];
    #pragma unroll
    for (int v = 0; v < 5; v++)
        hv[v] = __floats2half2_rn(z[2*v], z[2*v+1]);
    __half2* o = g_z3h + (size_t)i * 8;
    *(uint4*)(o) = *(uint4*)(hv);
    *(unsigned*)(o + 4) = *(unsigned*)(hv + 4);
}

__device__ __forceinline__ int lowerb(const int* __restrict__ a, int n, int v) {
    int lo = 0, hi = n;
    while (lo < hi) {
        int m = (lo + hi) >> 1;
        if (a[m] < v) lo = m + 1; else hi = m;
    }
    return lo;
}

// Layer 3b + pool + FUSED finalizer (last-block pattern).
// Also restores the zero-invariant on g_degin/g_degout/g_gsum/g_done.
__global__ void k_layer3(const int* __restrict__ gids, const float* __restrict__ b3,
                         float* __restrict__ out) {
    __shared__ float ssum[N_GRAPHS * 10];
    int t = threadIdx.x;
    for (int j = t; j < N_GRAPHS * 10; j += blockDim.x) ssum[j] = 0.f;
    __syncthreads();
    int i = blockIdx.x * blockDim.x + t;
    float v[10];
    int g = -1;
    if (i < N_NODES) {
        #pragma unroll
        for (int j = 0; j < 10; j++) v[j] = 0.f;
        int deg = g_degin[i];
        const int* row = g_ell + (size_t)i * ELL_W;
        int e = 0;
        for (; e + 4 <= deg; e += 4) {
            int4 s = *(const int4*)(row + e);
            const __half2* r0 = g_z3h + (size_t)s.x * 8;
            const __half2* r1 = g_z3h + (size_t)s.y * 8;
            const __half2* r2 = g_z3h + (size_t)s.z * 8;
            const __half2* r3 = g_z3h + (size_t)s.w * 8;
            uint4 u0 = *(const uint4*)r0;  unsigned w0 = *(const unsigned*)(r0 + 4);
            uint4 u1 = *(const uint4*)r1;  unsigned w1 = *(const unsigned*)(r1 + 4);
            uint4 u2 = *(const uint4*)r2;  unsigned w2 = *(const unsigned*)(r2 + 4);
            uint4 u3 = *(const uint4*)r3;  unsigned w3 = *(const unsigned*)(r3 + 4);
            acc_h2(v[0], v[1], u0.x); acc_h2(v[2], v[3], u0.y);
            acc_h2(v[4], v[5], u0.z); acc_h2(v[6], v[7], u0.w); acc_h2(v[8], v[9], w0);
            acc_h2(v[0], v[1], u1.x); acc_h2(v[2], v[3], u1.y);
            acc_h2(v[4], v[5], u1.z); acc_h2(v[6], v[7], u1.w); acc_h2(v[8], v[9], w1);
            acc_h2(v[0], v[1], u2.x); acc_h2(v[2], v[3], u2.y);
            acc_h2(v[4], v[5], u2.z); acc_h2(v[6], v[7], u2.w); acc_h2(v[8], v[9], w2);
            acc_h2(v[0], v[1], u3.x); acc_h2(v[2], v[3], u3.y);
            acc_h2(v[4], v[5], u3.z); acc_h2(v[6], v[7], u3.w); acc_h2(v[8], v[9], w3);
        }
        for (; e < deg; e++) {
            int s = row[e];
            const __half2* r = g_z3h + (size_t)s * 8;
            uint4 u = *(const uint4*)r;
            unsigned w = *(const unsigned*)(r + 4);
            acc_h2(v[0], v[1], u.x); acc_h2(v[2], v[3], u.y);
            acc_h2(v[4], v[5], u.z); acc_h2(v[6], v[7], u.w); acc_h2(v[8], v[9], w);
        }
        float ii = g_invin[i];
        #pragma unroll
        for (int j = 0; j < 10; j++) v[j] *= ii;
        g = gids[i];
        // restore zero-invariant for next call (degin already consumed above)
        g_degin[i]  = 0;
        g_degout[i] = 0;
    } else {
        #pragma unroll
        for (int j = 0; j < 10; j++) v[j] = 0.f;
    }
    int leader = __shfl_sync(0xffffffffu, g, 0);
    bool uni = __all_sync(0xffffffffu, g == leader);
    if (uni && leader >= 0) {
        #pragma unroll
        for (int j = 0; j < 10; j++) {
            float s = v[j];
            #pragma unroll
            for (int off = 16; off > 0; off >>= 1)
                s += __shfl_xor_sync(0xffffffffu, s, off);
            if ((t & 31) == 0) atomicAdd(&ssum[leader * 10 + j], s);
        }
    } else if (g >= 0) {
        #pragma unroll
        for (int j = 0; j < 10; j++)
            atomicAdd(&ssum[g * 10 + j], v[j]);
    }
    __syncthreads();
    for (int j = t; j < N_GRAPHS * 10; j += blockDim.x) {
        float s = ssum[j];
        if (s != 0.f) atomicAdd(&g_gsum[j], s);
    }
    // -------- last-block finalizer --------
    __threadfence();
    __shared__ int s_last;
    __syncthreads();
    if (t == 0) {
        int d = atomicAdd(&g_done, 1);
        s_last = (d == (int)gridDim.x - 1);
    }
    __syncthreads();
    if (s_last) {
        // all blocks' gsum atomics are visible (fence-before-done + atomic order)
        if (t < N_GRAPHS * 10) {
            int gg = t / 10, j = t % 10;
            int lo = lowerb(gids, N_NODES, gg);
            int hi = lowerb(gids, N_NODES, gg + 1);
            float cnt = (float)(hi - lo);
            out[t] = g_gsum[t] / fmaxf(cnt, 1.f) + b3[j];
            g_gsum[t] = 0.f;                 // restore invariant
        }
        if (t == 0) g_done = 0;              // restore invariant
    }
}

// ---------------- launch ------------------------------------------------------
extern "C" void kernel_launch(void* const* d_in, const int* in_sizes, int n_in,
                              void* d_out, int out_size) {
    const float* n_feat = (const float*)d_in[0];
    const int*   src    = (const int*)  d_in[1];
    const int*   dst    = (const int*)  d_in[2];
    const int*   gids   = (const int*)  d_in[3];
    const float* W1     = (const float*)d_in[4];
    const float* b1     = (const float*)d_in[5];
    const float* W2     = (const float*)d_in[6];
    const float* b2     = (const float*)d_in[7];
    const float* W3     = (const float*)d_in[8];
    const float* b3     = (const float*)d_in[9];
    float* out = (float*)d_out;

    const int TB = 256;
    const int nb  = (N_NODES + TB - 1) / TB;
    const int eb8 = (N_EDGES / 8 + TB - 1) / TB;
    const int pb  = (N_NODES + 1023) / 1024;

    k_fill   <<<eb8, TB>>>(src, dst);
    k_prep   <<<nb, TB>>>(n_feat);
    k_layer1 <<<nb, TB>>>(W1, b1);
    k_layer2 <<<nb, TB>>>(W2, b2, W3);
    k_layer3 <<<pb, 1024>>>(gids, b3, out);
}